// round 11
// baseline (speedup 1.0000x reference)
#include <cuda_runtime.h>
#include <cstdint>
#include <cstddef>

#define T_STEPS 2048
#define NB      32
#define HDIM    256
#define G4H     1024
#define CLUSTER_SZ 8

// ---------------------------------------------------------------------------
// Scratch (device globals — no allocation allowed in kernel_launch)
// ---------------------------------------------------------------------------
__device__ float g_xw0[(size_t)NB * T_STEPS * G4H];    // 268 MB
__device__ float g_h0seq[(size_t)NB * T_STEPS * HDIM]; // 64 MB
__device__ float g_xw1[(size_t)NB * T_STEPS * G4H];    // 268 MB
__device__ float g_h1T[NB * HDIM];

// ---------------------------------------------------------------------------
// Packed fp32x2 helpers (Blackwell FFMA2 path — ptxas won't auto-fuse)
// ---------------------------------------------------------------------------
__device__ __forceinline__ uint64_t fma_x2(uint64_t a, uint64_t b, uint64_t c) {
    uint64_t d;
    asm("fma.rn.f32x2 %0, %1, %2, %3;" : "=l"(d) : "l"(a), "l"(b), "l"(c));
    return d;
}
__device__ __forceinline__ uint64_t pack2(float x, float y) {
    uint64_t d;
    asm("mov.b64 %0, {%1, %2};" : "=l"(d) : "f"(x), "f"(y));
    return d;
}
__device__ __forceinline__ void unpack2(uint64_t v, float& lo, float& hi) {
    asm("mov.b64 {%0, %1}, %2;" : "=f"(lo), "=f"(hi) : "l"(v));
}
__device__ __forceinline__ void lds_v2u64(uint64_t& a, uint64_t& b, uint32_t addr) {
    asm volatile("ld.shared.v2.u64 {%0, %1}, [%2];" : "=l"(a), "=l"(b) : "r"(addr));
}

#define MBARRIER_INIT(addr, count) \
    asm volatile("mbarrier.init.shared.b64 [%0], %1;" \
                 :: "r"((uint32_t)(addr)), "r"((uint32_t)(count)) : "memory")

// Acquire at CLUSTER scope: pairs with producers' release-arrives.
#define MBARRIER_WAIT_PARITY_CL(mbar_smem_addr, phase_parity) do { \
    uint32_t _mbar = (uint32_t)(mbar_smem_addr); \
    uint32_t _parity = (uint32_t)(phase_parity); \
    uint32_t _done; \
    asm volatile( \
        "{\n\t" \
        ".reg .pred p;\n\t" \
        "mbarrier.try_wait.parity.acquire.cluster.shared::cta.b64 p, [%1], %2;\n\t" \
        "selp.b32 %0, 1, 0, p;\n\t" \
        "}" \
        : "=r"(_done) : "r"(_mbar), "r"(_parity) : "memory"); \
    if (!_done) { \
        asm volatile( \
            "{\n\t" \
            ".reg .pred P1;\n\t" \
            "WAIT_LOOP_%=:\n\t" \
            "mbarrier.try_wait.parity.acquire.cluster.shared::cta.b64 P1, [%0], %1, 0x989680;\n\t" \
            "@P1 bra.uni WAIT_DONE_%=;\n\t" \
            "bra.uni WAIT_LOOP_%=;\n\t" \
            "WAIT_DONE_%=:\n\t" \
            "}" \
            :: "r"(_mbar), "r"(_parity) : "memory"); \
    } \
} while(0)

#define CLUSTER_SYNC() do { \
    asm volatile("barrier.cluster.arrive.aligned;" ::: "memory"); \
    asm volatile("barrier.cluster.wait.aligned;"   ::: "memory"); \
} while (0)

// ---------------------------------------------------------------------------
// GEMM: out[M x 1024] = A[M x K] @ W[K x 1024] + bias   (M = 65536)
// ---------------------------------------------------------------------------
template <int K>
__global__ __launch_bounds__(256)
void gemm_xw(const float* __restrict__ A, const float* __restrict__ W,
             const float* __restrict__ bias, float* __restrict__ out) {
    extern __shared__ float sm[];
    float* a_s = sm;               // [128][65] transposed A tile
    float* w_s = sm + 128 * 65;    // [128][64]

    const int tid = threadIdx.x;
    const long m0 = (long)blockIdx.x * 64;
    const int  n0 = blockIdx.y * 64;

    const int tn = (tid & 15) << 2;
    const int tm = (tid >> 4) << 2;

    const uint32_t ws_b = (uint32_t)__cvta_generic_to_shared(w_s);

    uint64_t acc01[4], acc23[4];
#pragma unroll
    for (int i = 0; i < 4; i++) { acc01[i] = 0ull; acc23[i] = 0ull; }

    for (int k0 = 0; k0 < K; k0 += 128) {
        for (int idx = tid; idx < 64 * 128; idx += 256) {
            int r = idx >> 7;
            int k = idx & 127;
            a_s[k * 65 + r] = A[(m0 + r) * K + k0 + k];
        }
        for (int idx = tid; idx < 128 * 16; idx += 256) {
            int k = idx >> 4, c4 = idx & 15;
            *reinterpret_cast<float4*>(w_s + k * 64 + c4 * 4) =
                *reinterpret_cast<const float4*>(W + (size_t)(k0 + k) * G4H + n0 + c4 * 4);
        }
        __syncthreads();

#pragma unroll 8
        for (int k = 0; k < 128; k++) {
            const float* ap = a_s + k * 65 + tm;
            float a0 = ap[0], a1 = ap[1], a2 = ap[2], a3 = ap[3];
            uint64_t b01, b23;
            lds_v2u64(b01, b23, ws_b + (uint32_t)(k * 64 + tn) * 4u);
            uint64_t aa;
            aa = pack2(a0, a0);
            acc01[0] = fma_x2(aa, b01, acc01[0]); acc23[0] = fma_x2(aa, b23, acc23[0]);
            aa = pack2(a1, a1);
            acc01[1] = fma_x2(aa, b01, acc01[1]); acc23[1] = fma_x2(aa, b23, acc23[1]);
            aa = pack2(a2, a2);
            acc01[2] = fma_x2(aa, b01, acc01[2]); acc23[2] = fma_x2(aa, b23, acc23[2]);
            aa = pack2(a3, a3);
            acc01[3] = fma_x2(aa, b01, acc01[3]); acc23[3] = fma_x2(aa, b23, acc23[3]);
        }
        __syncthreads();
    }

    float4 bv = *reinterpret_cast<const float4*>(bias + n0 + tn);
#pragma unroll
    for (int i = 0; i < 4; i++) {
        float4 o;
        unpack2(acc01[i], o.x, o.y);
        unpack2(acc23[i], o.z, o.w);
        o.x += bv.x; o.y += bv.y; o.z += bv.z; o.w += bv.w;
        *reinterpret_cast<float4*>(out + (m0 + tm + i) * G4H + n0 + tn) = o;
    }
}

// ---------------------------------------------------------------------------
// LSTM recurrence — R10 structure (4-way k-split, register-resident U, push
// signaling) with WARP-SHUFFLE SEND AGGREGATION:
// after combine, lane cu gathers its 8-unit segment (seg = cu&3) via 8
// register shuffles and sends it to ONE peer (pr = cu>>2) as 2 x
// st.shared::cluster.v4 + 1 same-thread release-arrive. Messages per step:
// remote stores 512 -> 128, arrives per destination mbar 512 -> 64 (the
// R10 spine binder: same-address arrive processing ~4cyc each). No
// bar.sync / fence / pull added (R5-R7 proved those regress).
// ---------------------------------------------------------------------------
__device__ __forceinline__ float sigmoidf_(float x) {
    return __fdividef(1.f, 1.f + __expf(-x));
}

#define HBUF_OFF    0                             // [2 parity][2 batch][256]
#define PART_OFF    (2 * 2 * HDIM)                // [4 kq][4 gate][2 b][32]
#define MBAR_OFF    (PART_OFF + 1024)             // 2 x u64 (8B aligned)
#define REC_FLOATS  (MBAR_OFF + 8)
#define REC_THREADS 512

template <bool STORE_SEQ>
__global__ __launch_bounds__(REC_THREADS, 1) __cluster_dims__(CLUSTER_SZ, 1, 1)
void lstm_rec(const float* __restrict__ xw, const float* __restrict__ U,
              float* __restrict__ out_seq, float* __restrict__ out_last) {
    extern __shared__ float sm[];
    float* hbuf = sm + HBUF_OFF;
    float* part = sm + PART_OFF;

    const int tid = threadIdx.x;        // 512
    const int kq  = tid >> 7;           // k-quarter 0..3
    const int g   = (tid >> 5) & 3;     // gate 0..3 (i,f,g,o)
    const int u   = tid & 31;           // unit within CTA slice

    uint32_t rank;
    asm("mov.u32 %0, %%cluster_ctarank;" : "=r"(rank));
    const int cid = blockIdx.x >> 3;
    const int u0  = (int)rank * 32;
    const int b0  = cid * 2;

    const uint32_t smem_b = (uint32_t)__cvta_generic_to_shared(sm);
    const uint32_t mbar_b = smem_b + MBAR_OFF * 4u;
    const uint32_t hbuf_b = smem_b + HBUF_OFF * 4u;

    if (tid == 0) {
        MBARRIER_INIT(mbar_b,      64);   // parity 0: 8 lanes x 8 producers
        MBARRIER_INIT(mbar_b + 8,  64);   // parity 1
    }

    // ---- This thread's 64 U weights -> 32 packed f32x2 registers.
    const int gcol = g * HDIM + u0 + u;
    uint64_t wreg[32];
    {
        const float* Up = U + (size_t)(kq * 64) * G4H + gcol;
#pragma unroll
        for (int k4 = 0; k4 < 16; k4++) {
            float w0 = Up[(k4 * 4 + 0) * G4H];
            float w1 = Up[(k4 * 4 + 1) * G4H];
            float w2 = Up[(k4 * 4 + 2) * G4H];
            float w3 = Up[(k4 * 4 + 3) * G4H];
            wreg[k4 * 2 + 0] = pack2(w0, w1);
            wreg[k4 * 2 + 1] = pack2(w2, w3);
        }
    }

    // Zero h double-buffer + partials
    for (int idx = tid; idx < 2 * 2 * HDIM + 1024; idx += REC_THREADS)
        hbuf[idx] = 0.f;
    __syncthreads();

    // Combine-thread state (warps 0/1)
    const bool is_comb = (tid < 64);
    const int  cb  = tid >> 5;          // batch within pair
    const int  cu  = tid & 31;          // unit
    const int  seg = cu & 3;            // 8-unit segment this lane sends
    const int  pr  = cu >> 2;           // the ONE peer this lane signals
    float cst = 0.f;
    float xwr0 = 0.f, xwr1 = 0.f, xwr2 = 0.f, xwr3 = 0.f;
    const size_t xbase = (size_t)(b0 + cb) * T_STEPS * G4H + u0 + cu;
    uint32_t ra_peer = 0;
    if (is_comb) {
        xwr0 = xw[xbase + 0 * HDIM];
        xwr1 = xw[xbase + 1 * HDIM];
        xwr2 = xw[xbase + 2 * HDIM];
        xwr3 = xw[xbase + 3 * HDIM];
        asm volatile("mapa.shared::cluster.u32 %0, %1, %2;"
                     : "=r"(ra_peer) : "r"(smem_b), "r"(pr));
    }

    // mbarriers + zeroed hbuf must be cluster-visible before any peer store.
    CLUSTER_SYNC();

    int ph0 = 0, ph1 = 0;

    for (int t = 0; t < T_STEPS; t++) {
        // Wait for h(t-1): lives in buf[(t+1)&1], signaled on mbar[(t+1)&1]
        if (t > 0) {
            if (t & 1) { MBARRIER_WAIT_PARITY_CL(mbar_b,     ph0); ph0 ^= 1; }
            else       { MBARRIER_WAIT_PARITY_CL(mbar_b + 8, ph1); ph1 ^= 1; }
        }

        const int rd = (t + 1) & 1;
        const uint32_t h0_b = hbuf_b + (uint32_t)(rd * 2 * HDIM + kq * 64) * 4u;
        const uint32_t h1_b = h0_b + HDIM * 4u;

        uint64_t a01 = 0ull, a23 = 0ull, c01 = 0ull, c23 = 0ull;
#pragma unroll
        for (int k4 = 0; k4 < 16; k4++) {
            uint64_t p01, p23, q01, q23;
            lds_v2u64(p01, p23, h0_b + (uint32_t)k4 * 16u);  // broadcast
            lds_v2u64(q01, q23, h1_b + (uint32_t)k4 * 16u);  // broadcast
            a01 = fma_x2(wreg[k4 * 2 + 0], p01, a01);
            a23 = fma_x2(wreg[k4 * 2 + 1], p23, a23);
            c01 = fma_x2(wreg[k4 * 2 + 0], q01, c01);
            c23 = fma_x2(wreg[k4 * 2 + 1], q23, c23);
        }
        float s0, s1, s2, s3, r0, r1, r2, r3;
        unpack2(a01, s0, s1); unpack2(a23, s2, s3);
        unpack2(c01, r0, r1); unpack2(c23, r2, r3);
        float pa = (s0 + s1) + (s2 + s3);
        float pb = (r0 + r1) + (r2 + r3);

        // part[kq][gate][batch][unit] — u consecutive per warp: conflict-free
        part[((kq * 4 + g) * 2 + 0) * 32 + u] = pa;
        part[((kq * 4 + g) * 2 + 1) * 32 + u] = pb;
        __syncthreads();

        if (is_comb) {
            float zi = xwr0, zf = xwr1, zg = xwr2, zo = xwr3;
#pragma unroll
            for (int q = 0; q < 4; q++) {
                zi += part[((q * 4 + 0) * 2 + cb) * 32 + cu];
                zf += part[((q * 4 + 1) * 2 + cb) * 32 + cu];
                zg += part[((q * 4 + 2) * 2 + cb) * 32 + cu];
                zo += part[((q * 4 + 3) * 2 + cb) * 32 + cu];
            }

            float iv = sigmoidf_(zi);
            float fv = sigmoidf_(zf);
            float ov = sigmoidf_(zo);
            cst = fmaf(fv, cst, iv * zg);  // linear candidate activation
            float h = ov * cst;            // linear output activation

            if (STORE_SEQ) {
                out_seq[((size_t)(b0 + cb) * T_STEPS + t) * HDIM + u0 + cu] = h;
            } else if (t == T_STEPS - 1) {
                out_last[(b0 + cb) * HDIM + u0 + cu] = h;
            }

            if (t + 1 < T_STEPS) {
                // Shuffle-gather this lane's 8-unit segment (registers only).
                float h0s = __shfl_sync(0xffffffffu, h, seg * 8 + 0);
                float h1s = __shfl_sync(0xffffffffu, h, seg * 8 + 1);
                float h2s = __shfl_sync(0xffffffffu, h, seg * 8 + 2);
                float h3s = __shfl_sync(0xffffffffu, h, seg * 8 + 3);
                float h4s = __shfl_sync(0xffffffffu, h, seg * 8 + 4);
                float h5s = __shfl_sync(0xffffffffu, h, seg * 8 + 5);
                float h6s = __shfl_sync(0xffffffffu, h, seg * 8 + 6);
                float h7s = __shfl_sync(0xffffffffu, h, seg * 8 + 7);

                // 2 x 16B push to the ONE peer, then 1 release-arrive
                // (same-thread ordering; covers exactly these stores).
                const uint32_t dst = ra_peer + HBUF_OFF * 4u +
                    (uint32_t)((t & 1) * 2 * HDIM + cb * HDIM + u0 + seg * 8) * 4u;
                asm volatile("st.shared::cluster.v4.f32 [%0], {%1,%2,%3,%4};"
                             :: "r"(dst), "f"(h0s), "f"(h1s), "f"(h2s), "f"(h3s)
                             : "memory");
                asm volatile("st.shared::cluster.v4.f32 [%0], {%1,%2,%3,%4};"
                             :: "r"(dst + 16u), "f"(h4s), "f"(h5s), "f"(h6s), "f"(h7s)
                             : "memory");
                asm volatile("mbarrier.arrive.release.cluster.shared::cluster.b64 _, [%0];"
                             :: "r"(ra_peer + MBAR_OFF * 4u + ((uint32_t)(t & 1) << 3))
                             : "memory");
            }

            // prefetch next step's xw (after the signal is on the wire)
            if (t + 1 < T_STEPS) {
                const size_t xb = xbase + (size_t)(t + 1) * G4H;
                xwr0 = xw[xb + 0 * HDIM];
                xwr1 = xw[xb + 1 * HDIM];
                xwr2 = xw[xb + 2 * HDIM];
                xwr3 = xw[xb + 3 * HDIM];
            }
        }
        // No end-of-step barrier: next-step part/hbuf writes are ordered
        // behind the mbar wait (which requires this CTA's own arrives).
    }
}

// ---------------------------------------------------------------------------
// Final FC: out[32,1,128] = h1T[32,256] @ Wfc[256,128] + bfc
// ---------------------------------------------------------------------------
__global__ __launch_bounds__(128)
void fc_kernel(const float* __restrict__ h, const float* __restrict__ Wfc,
               const float* __restrict__ bfc, float* __restrict__ out) {
    const int b = blockIdx.x;
    const int j = threadIdx.x;
    const float* hb = h + b * HDIM;
    float acc = bfc[j];
#pragma unroll 16
    for (int k = 0; k < HDIM; k++)
        acc = fmaf(hb[k], Wfc[k * 128 + j], acc);
    out[b * 128 + j] = acc;
}

// ---------------------------------------------------------------------------
// Launch
// ---------------------------------------------------------------------------
#define GEMM_SMEM ((128 * 65 + 128 * 64) * 4)   // 66048
#define REC_SMEM  (REC_FLOATS * 4)              // ~8 KB

extern "C" void kernel_launch(void* const* d_in, const int* in_sizes, int n_in,
                              void* d_out, int out_size) {
    const float* x   = (const float*)d_in[0];
    const float* W0  = (const float*)d_in[1];
    const float* U0  = (const float*)d_in[2];
    const float* b0v = (const float*)d_in[3];
    const float* W1  = (const float*)d_in[4];
    const float* U1  = (const float*)d_in[5];
    const float* b1v = (const float*)d_in[6];
    const float* Wfc = (const float*)d_in[7];
    const float* bfc = (const float*)d_in[8];
    float* out = (float*)d_out;

    float *xw0, *h0seq, *xw1, *h1T;
    cudaGetSymbolAddress((void**)&xw0,   g_xw0);
    cudaGetSymbolAddress((void**)&h0seq, g_h0seq);
    cudaGetSymbolAddress((void**)&xw1,   g_xw1);
    cudaGetSymbolAddress((void**)&h1T,   g_h1T);

    cudaFuncSetAttribute(gemm_xw<128>, cudaFuncAttributeMaxDynamicSharedMemorySize, GEMM_SMEM);
    cudaFuncSetAttribute(gemm_xw<256>, cudaFuncAttributeMaxDynamicSharedMemorySize, GEMM_SMEM);
    cudaFuncSetAttribute(lstm_rec<true>,  cudaFuncAttributeMaxDynamicSharedMemorySize, REC_SMEM);
    cudaFuncSetAttribute(lstm_rec<false>, cudaFuncAttributeMaxDynamicSharedMemorySize, REC_SMEM);

    const long M = (long)NB * T_STEPS;  // 65536 rows

    gemm_xw<128><<<dim3((unsigned)(M / 64), G4H / 64), 256, GEMM_SMEM>>>(x, W0, b0v, xw0);
    lstm_rec<true><<<NB / 2 * CLUSTER_SZ, REC_THREADS, REC_SMEM>>>(xw0, U0, h0seq, nullptr);
    gemm_xw<256><<<dim3((unsigned)(M / 64), G4H / 64), 256, GEMM_SMEM>>>(h0seq, W1, b1v, xw1);
    lstm_rec<false><<<NB / 2 * CLUSTER_SZ, REC_THREADS, REC_SMEM>>>(xw1, U1, nullptr, h1T);
    fc_kernel<<<NB, 128>>>(h1T, Wfc, bfc, out);
}

// round 12
// speedup vs baseline: 1.6002x; 1.6002x over previous
#include <cuda_runtime.h>
#include <cstdint>
#include <cstddef>

#define T_STEPS 2048
#define NB      32
#define HDIM    256
#define G4H     1024
#define CLUSTER_SZ 8

// ---------------------------------------------------------------------------
// Scratch (device globals — no allocation allowed in kernel_launch)
// ---------------------------------------------------------------------------
__device__ float g_xw0[(size_t)NB * T_STEPS * G4H];    // 268 MB
__device__ float g_h0seq[(size_t)NB * T_STEPS * HDIM]; // 64 MB
__device__ float g_xw1[(size_t)NB * T_STEPS * G4H];    // 268 MB
__device__ float g_h1T[NB * HDIM];

// ---------------------------------------------------------------------------
// Packed fp32x2 helpers (Blackwell FFMA2 path — ptxas won't auto-fuse)
// ---------------------------------------------------------------------------
__device__ __forceinline__ uint64_t fma_x2(uint64_t a, uint64_t b, uint64_t c) {
    uint64_t d;
    asm("fma.rn.f32x2 %0, %1, %2, %3;" : "=l"(d) : "l"(a), "l"(b), "l"(c));
    return d;
}
__device__ __forceinline__ uint64_t pack2(float x, float y) {
    uint64_t d;
    asm("mov.b64 %0, {%1, %2};" : "=l"(d) : "f"(x), "f"(y));
    return d;
}
__device__ __forceinline__ void unpack2(uint64_t v, float& lo, float& hi) {
    asm("mov.b64 {%0, %1}, %2;" : "=f"(lo), "=f"(hi) : "l"(v));
}
__device__ __forceinline__ void lds_v2u64(uint64_t& a, uint64_t& b, uint32_t addr) {
    asm volatile("ld.shared.v2.u64 {%0, %1}, [%2];" : "=l"(a), "=l"(b) : "r"(addr));
}

#define MBARRIER_INIT(addr, count) \
    asm volatile("mbarrier.init.shared.b64 [%0], %1;" \
                 :: "r"((uint32_t)(addr)), "r"((uint32_t)(count)) : "memory")

// acquire.cta wait — the R4/R9/R10 proven-fast form. (acquire.cluster was
// the R11 poison: ~UCGABAR-class cost per thread per step.)
#define MBARRIER_WAIT_PARITY(mbar_smem_addr, phase_parity) do { \
    uint32_t _mbar = (uint32_t)(mbar_smem_addr); \
    uint32_t _parity = (uint32_t)(phase_parity); \
    uint32_t _done; \
    asm volatile( \
        "{\n\t" \
        ".reg .pred p;\n\t" \
        "mbarrier.try_wait.parity.acquire.cta.shared::cta.b64 p, [%1], %2;\n\t" \
        "selp.b32 %0, 1, 0, p;\n\t" \
        "}" \
        : "=r"(_done) : "r"(_mbar), "r"(_parity) : "memory"); \
    if (!_done) { \
        asm volatile( \
            "{\n\t" \
            ".reg .pred P1;\n\t" \
            "WAIT_LOOP_%=:\n\t" \
            "mbarrier.try_wait.parity.acquire.cta.shared::cta.b64 P1, [%0], %1, 0x989680;\n\t" \
            "@P1 bra.uni WAIT_DONE_%=;\n\t" \
            "bra.uni WAIT_LOOP_%=;\n\t" \
            "WAIT_DONE_%=:\n\t" \
            "}" \
            :: "r"(_mbar), "r"(_parity) : "memory"); \
    } \
} while(0)

#define CLUSTER_SYNC() do { \
    asm volatile("barrier.cluster.arrive.aligned;" ::: "memory"); \
    asm volatile("barrier.cluster.wait.aligned;"   ::: "memory"); \
} while (0)

// ---------------------------------------------------------------------------
// GEMM: out[M x 1024] = A[M x K] @ W[K x 1024] + bias   (M = 65536)
// ---------------------------------------------------------------------------
template <int K>
__global__ __launch_bounds__(256)
void gemm_xw(const float* __restrict__ A, const float* __restrict__ W,
             const float* __restrict__ bias, float* __restrict__ out) {
    extern __shared__ float sm[];
    float* a_s = sm;               // [128][65] transposed A tile
    float* w_s = sm + 128 * 65;    // [128][64]

    const int tid = threadIdx.x;
    const long m0 = (long)blockIdx.x * 64;
    const int  n0 = blockIdx.y * 64;

    const int tn = (tid & 15) << 2;
    const int tm = (tid >> 4) << 2;

    const uint32_t ws_b = (uint32_t)__cvta_generic_to_shared(w_s);

    uint64_t acc01[4], acc23[4];
#pragma unroll
    for (int i = 0; i < 4; i++) { acc01[i] = 0ull; acc23[i] = 0ull; }

    for (int k0 = 0; k0 < K; k0 += 128) {
        for (int idx = tid; idx < 64 * 128; idx += 256) {
            int r = idx >> 7;
            int k = idx & 127;
            a_s[k * 65 + r] = A[(m0 + r) * K + k0 + k];
        }
        for (int idx = tid; idx < 128 * 16; idx += 256) {
            int k = idx >> 4, c4 = idx & 15;
            *reinterpret_cast<float4*>(w_s + k * 64 + c4 * 4) =
                *reinterpret_cast<const float4*>(W + (size_t)(k0 + k) * G4H + n0 + c4 * 4);
        }
        __syncthreads();

#pragma unroll 8
        for (int k = 0; k < 128; k++) {
            const float* ap = a_s + k * 65 + tm;
            float a0 = ap[0], a1 = ap[1], a2 = ap[2], a3 = ap[3];
            uint64_t b01, b23;
            lds_v2u64(b01, b23, ws_b + (uint32_t)(k * 64 + tn) * 4u);
            uint64_t aa;
            aa = pack2(a0, a0);
            acc01[0] = fma_x2(aa, b01, acc01[0]); acc23[0] = fma_x2(aa, b23, acc23[0]);
            aa = pack2(a1, a1);
            acc01[1] = fma_x2(aa, b01, acc01[1]); acc23[1] = fma_x2(aa, b23, acc23[1]);
            aa = pack2(a2, a2);
            acc01[2] = fma_x2(aa, b01, acc01[2]); acc23[2] = fma_x2(aa, b23, acc23[2]);
            aa = pack2(a3, a3);
            acc01[3] = fma_x2(aa, b01, acc01[3]); acc23[3] = fma_x2(aa, b23, acc23[3]);
        }
        __syncthreads();
    }

    float4 bv = *reinterpret_cast<const float4*>(bias + n0 + tn);
#pragma unroll
    for (int i = 0; i < 4; i++) {
        float4 o;
        unpack2(acc01[i], o.x, o.y);
        unpack2(acc23[i], o.z, o.w);
        o.x += bv.x; o.y += bv.y; o.z += bv.z; o.w += bv.w;
        *reinterpret_cast<float4*>(out + (m0 + tm + i) * G4H + n0 + tn) = o;
    }
}

// ---------------------------------------------------------------------------
// LSTM recurrence — R10 structure (4-way k-split, register-resident U,
// plain-arrive push, acquire.cta waits) with AGGREGATED SENDS:
// combine threads STS h to a local stage, __syncwarp, then lanes 0..7 of
// each combine warp each push the warp's full 128B batch-slice to ONE peer
// (8 broadcast LDS.128 + 8 st.shared::cluster.v4) + 1 plain arrive
// (same-thread store->arrive ordering, the R4/R9/R10-proven form).
// Destination port traffic per step: 1024 ops -> 128 v4-stores + 16 arrives.
// NO shuffles, NO release/acquire.cluster, NO bar.sync (R5/R7/R11 poisons).
// ---------------------------------------------------------------------------
__device__ __forceinline__ float sigmoidf_(float x) {
    return __fdividef(1.f, 1.f + __expf(-x));
}

#define HBUF_OFF    0                             // [2 parity][2 batch][256]
#define STAGE_OFF   (2 * 2 * HDIM)                // [2 parity][2 batch][32]
#define PART_OFF    (STAGE_OFF + 128)             // [4 kq][4 gate][2 b][32]
#define MBAR_OFF    (PART_OFF + 1024)             // 2 x u64 (8B aligned)
#define REC_FLOATS  (MBAR_OFF + 8)
#define REC_THREADS 512

template <bool STORE_SEQ>
__global__ __launch_bounds__(REC_THREADS, 1) __cluster_dims__(CLUSTER_SZ, 1, 1)
void lstm_rec(const float* __restrict__ xw, const float* __restrict__ U,
              float* __restrict__ out_seq, float* __restrict__ out_last) {
    extern __shared__ float sm[];
    float* hbuf = sm + HBUF_OFF;
    float* part = sm + PART_OFF;

    const int tid = threadIdx.x;        // 512
    const int kq  = tid >> 7;           // k-quarter 0..3
    const int g   = (tid >> 5) & 3;     // gate 0..3 (i,f,g,o)
    const int u   = tid & 31;           // unit within CTA slice

    uint32_t rank;
    asm("mov.u32 %0, %%cluster_ctarank;" : "=r"(rank));
    const int cid = blockIdx.x >> 3;
    const int u0  = (int)rank * 32;
    const int b0  = cid * 2;

    const uint32_t smem_b  = (uint32_t)__cvta_generic_to_shared(sm);
    const uint32_t mbar_b  = smem_b + MBAR_OFF * 4u;
    const uint32_t hbuf_b  = smem_b + HBUF_OFF * 4u;
    const uint32_t stage_b = smem_b + STAGE_OFF * 4u;

    if (tid == 0) {
        MBARRIER_INIT(mbar_b,      16);   // parity 0: 8 CTAs x 2 warps
        MBARRIER_INIT(mbar_b + 8,  16);   // parity 1
    }

    // ---- This thread's 64 U weights -> 32 packed f32x2 registers.
    const int gcol = g * HDIM + u0 + u;
    uint64_t wreg[32];
    {
        const float* Up = U + (size_t)(kq * 64) * G4H + gcol;
#pragma unroll
        for (int k4 = 0; k4 < 16; k4++) {
            float w0 = Up[(k4 * 4 + 0) * G4H];
            float w1 = Up[(k4 * 4 + 1) * G4H];
            float w2 = Up[(k4 * 4 + 2) * G4H];
            float w3 = Up[(k4 * 4 + 3) * G4H];
            wreg[k4 * 2 + 0] = pack2(w0, w1);
            wreg[k4 * 2 + 1] = pack2(w2, w3);
        }
    }

    // Zero h double-buffer + stage + partials
    for (int idx = tid; idx < 2 * 2 * HDIM + 128 + 1024; idx += REC_THREADS)
        hbuf[idx] = 0.f;
    __syncthreads();

    // Combine-thread state (warps 0/1)
    const bool is_comb = (tid < 64);
    const int  cb  = tid >> 5;          // batch within pair
    const int  cu  = tid & 31;          // unit
    float cst = 0.f;
    float xwr0 = 0.f, xwr1 = 0.f, xwr2 = 0.f, xwr3 = 0.f;
    const size_t xbase = (size_t)(b0 + cb) * T_STEPS * G4H + u0 + cu;
    uint32_t ra_peer = 0;               // lanes 0..7: the one peer they serve
    if (is_comb) {
        xwr0 = xw[xbase + 0 * HDIM];
        xwr1 = xw[xbase + 1 * HDIM];
        xwr2 = xw[xbase + 2 * HDIM];
        xwr3 = xw[xbase + 3 * HDIM];
        if (cu < CLUSTER_SZ) {
            asm volatile("mapa.shared::cluster.u32 %0, %1, %2;"
                         : "=r"(ra_peer) : "r"(smem_b), "r"(cu));
        }
    }

    // mbarriers + zeroed hbuf must be cluster-visible before any peer store.
    CLUSTER_SYNC();

    int ph0 = 0, ph1 = 0;

    for (int t = 0; t < T_STEPS; t++) {
        // Wait for h(t-1): lives in buf[(t+1)&1], signaled on mbar[(t+1)&1]
        if (t > 0) {
            if (t & 1) { MBARRIER_WAIT_PARITY(mbar_b,     ph0); ph0 ^= 1; }
            else       { MBARRIER_WAIT_PARITY(mbar_b + 8, ph1); ph1 ^= 1; }
        }

        const int rd = (t + 1) & 1;
        const uint32_t h0_b = hbuf_b + (uint32_t)(rd * 2 * HDIM + kq * 64) * 4u;
        const uint32_t h1_b = h0_b + HDIM * 4u;

        uint64_t a01 = 0ull, a23 = 0ull, c01 = 0ull, c23 = 0ull;
#pragma unroll
        for (int k4 = 0; k4 < 16; k4++) {
            uint64_t p01, p23, q01, q23;
            lds_v2u64(p01, p23, h0_b + (uint32_t)k4 * 16u);  // broadcast
            lds_v2u64(q01, q23, h1_b + (uint32_t)k4 * 16u);  // broadcast
            a01 = fma_x2(wreg[k4 * 2 + 0], p01, a01);
            a23 = fma_x2(wreg[k4 * 2 + 1], p23, a23);
            c01 = fma_x2(wreg[k4 * 2 + 0], q01, c01);
            c23 = fma_x2(wreg[k4 * 2 + 1], q23, c23);
        }
        float s0, s1, s2, s3, r0, r1, r2, r3;
        unpack2(a01, s0, s1); unpack2(a23, s2, s3);
        unpack2(c01, r0, r1); unpack2(c23, r2, r3);
        float pa = (s0 + s1) + (s2 + s3);
        float pb = (r0 + r1) + (r2 + r3);

        // part[kq][gate][batch][unit] — u consecutive per warp: conflict-free
        part[((kq * 4 + g) * 2 + 0) * 32 + u] = pa;
        part[((kq * 4 + g) * 2 + 1) * 32 + u] = pb;
        __syncthreads();

        if (is_comb) {
            float zi = xwr0, zf = xwr1, zg = xwr2, zo = xwr3;
#pragma unroll
            for (int q = 0; q < 4; q++) {
                zi += part[((q * 4 + 0) * 2 + cb) * 32 + cu];
                zf += part[((q * 4 + 1) * 2 + cb) * 32 + cu];
                zg += part[((q * 4 + 2) * 2 + cb) * 32 + cu];
                zo += part[((q * 4 + 3) * 2 + cb) * 32 + cu];
            }

            float iv = sigmoidf_(zi);
            float fv = sigmoidf_(zf);
            float ov = sigmoidf_(zo);
            cst = fmaf(fv, cst, iv * zg);  // linear candidate activation
            float h = ov * cst;            // linear output activation

            if (STORE_SEQ) {
                out_seq[((size_t)(b0 + cb) * T_STEPS + t) * HDIM + u0 + cu] = h;
            } else if (t == T_STEPS - 1) {
                out_last[(b0 + cb) * HDIM + u0 + cu] = h;
            }

            if (t + 1 < T_STEPS) {
                // Stage h locally, warp-sync, then lanes 0..7 each push this
                // warp's 128B batch-slice to ONE peer + 1 plain arrive.
                const uint32_t st_addr = stage_b +
                    (uint32_t)((t & 1) * 64 + cb * 32 + cu) * 4u;
                asm volatile("st.shared.f32 [%0], %1;"
                             :: "r"(st_addr), "f"(h) : "memory");
                __syncwarp();

                if (cu < CLUSTER_SZ) {
                    const uint32_t src0 = stage_b +
                        (uint32_t)((t & 1) * 64 + cb * 32) * 4u;
                    const uint32_t dst0 = ra_peer + HBUF_OFF * 4u +
                        (uint32_t)((t & 1) * 2 * HDIM + cb * HDIM + u0) * 4u;
#pragma unroll
                    for (int j = 0; j < 8; j++) {   // 8 x 16B = 128B slice
                        float4 v;
                        asm volatile("ld.shared.v4.f32 {%0,%1,%2,%3}, [%4];"
                                     : "=f"(v.x), "=f"(v.y), "=f"(v.z), "=f"(v.w)
                                     : "r"(src0 + (uint32_t)j * 16u));
                        asm volatile("st.shared::cluster.v4.f32 [%0], {%1,%2,%3,%4};"
                                     :: "r"(dst0 + (uint32_t)j * 16u),
                                        "f"(v.x), "f"(v.y), "f"(v.z), "f"(v.w)
                                     : "memory");
                    }
                    // Plain arrive: same-thread ordering of the stores above
                    // (R4/R9/R10-proven form; no .release.cluster).
                    asm volatile("mbarrier.arrive.shared::cluster.b64 _, [%0];"
                                 :: "r"(ra_peer + MBAR_OFF * 4u +
                                        ((uint32_t)(t & 1) << 3))
                                 : "memory");
                }
            }

            // prefetch next step's xw (after the signal is on the wire)
            if (t + 1 < T_STEPS) {
                const size_t xb = xbase + (size_t)(t + 1) * G4H;
                xwr0 = xw[xb + 0 * HDIM];
                xwr1 = xw[xb + 1 * HDIM];
                xwr2 = xw[xb + 2 * HDIM];
                xwr3 = xw[xb + 3 * HDIM];
            }
        }
        // No end-of-step barrier: next-step part/hbuf/stage writes are
        // ordered behind the mbar wait (requires this CTA's own arrives).
    }
}

// ---------------------------------------------------------------------------
// Final FC: out[32,1,128] = h1T[32,256] @ Wfc[256,128] + bfc
// ---------------------------------------------------------------------------
__global__ __launch_bounds__(128)
void fc_kernel(const float* __restrict__ h, const float* __restrict__ Wfc,
               const float* __restrict__ bfc, float* __restrict__ out) {
    const int b = blockIdx.x;
    const int j = threadIdx.x;
    const float* hb = h + b * HDIM;
    float acc = bfc[j];
#pragma unroll 16
    for (int k = 0; k < HDIM; k++)
        acc = fmaf(hb[k], Wfc[k * 128 + j], acc);
    out[b * 128 + j] = acc;
}

// ---------------------------------------------------------------------------
// Launch
// ---------------------------------------------------------------------------
#define GEMM_SMEM ((128 * 65 + 128 * 64) * 4)   // 66048
#define REC_SMEM  (REC_FLOATS * 4)              // ~9 KB

extern "C" void kernel_launch(void* const* d_in, const int* in_sizes, int n_in,
                              void* d_out, int out_size) {
    const float* x   = (const float*)d_in[0];
    const float* W0  = (const float*)d_in[1];
    const float* U0  = (const float*)d_in[2];
    const float* b0v = (const float*)d_in[3];
    const float* W1  = (const float*)d_in[4];
    const float* U1  = (const float*)d_in[5];
    const float* b1v = (const float*)d_in[6];
    const float* Wfc = (const float*)d_in[7];
    const float* bfc = (const float*)d_in[8];
    float* out = (float*)d_out;

    float *xw0, *h0seq, *xw1, *h1T;
    cudaGetSymbolAddress((void**)&xw0,   g_xw0);
    cudaGetSymbolAddress((void**)&h0seq, g_h0seq);
    cudaGetSymbolAddress((void**)&xw1,   g_xw1);
    cudaGetSymbolAddress((void**)&h1T,   g_h1T);

    cudaFuncSetAttribute(gemm_xw<128>, cudaFuncAttributeMaxDynamicSharedMemorySize, GEMM_SMEM);
    cudaFuncSetAttribute(gemm_xw<256>, cudaFuncAttributeMaxDynamicSharedMemorySize, GEMM_SMEM);
    cudaFuncSetAttribute(lstm_rec<true>,  cudaFuncAttributeMaxDynamicSharedMemorySize, REC_SMEM);
    cudaFuncSetAttribute(lstm_rec<false>, cudaFuncAttributeMaxDynamicSharedMemorySize, REC_SMEM);

    const long M = (long)NB * T_STEPS;  // 65536 rows

    gemm_xw<128><<<dim3((unsigned)(M / 64), G4H / 64), 256, GEMM_SMEM>>>(x, W0, b0v, xw0);
    lstm_rec<true><<<NB / 2 * CLUSTER_SZ, REC_THREADS, REC_SMEM>>>(xw0, U0, h0seq, nullptr);
    gemm_xw<256><<<dim3((unsigned)(M / 64), G4H / 64), 256, GEMM_SMEM>>>(h0seq, W1, b1v, xw1);
    lstm_rec<false><<<NB / 2 * CLUSTER_SZ, REC_THREADS, REC_SMEM>>>(xw1, U1, nullptr, h1T);
    fc_kernel<<<NB, 128>>>(h1T, Wfc, bfc, out);
}

// round 16
// speedup vs baseline: 1.8279x; 1.1423x over previous
#include <cuda_runtime.h>
#include <cstdint>
#include <cstddef>

#define T_STEPS 2048
#define NB      32
#define HDIM    256
#define G4H     1024
#define CLUSTER_SZ 8

// ---------------------------------------------------------------------------
// Scratch (device globals — no allocation allowed in kernel_launch)
// ---------------------------------------------------------------------------
__device__ float g_xw0[(size_t)NB * T_STEPS * G4H];    // 268 MB
__device__ float g_h0seq[(size_t)NB * T_STEPS * HDIM]; // 64 MB
__device__ float g_xw1[(size_t)NB * T_STEPS * G4H];    // 268 MB
__device__ float g_h1T[NB * HDIM];

// ---------------------------------------------------------------------------
// Packed fp32x2 helpers (Blackwell FFMA2 path — ptxas won't auto-fuse)
// ---------------------------------------------------------------------------
__device__ __forceinline__ uint64_t fma_x2(uint64_t a, uint64_t b, uint64_t c) {
    uint64_t d;
    asm("fma.rn.f32x2 %0, %1, %2, %3;" : "=l"(d) : "l"(a), "l"(b), "l"(c));
    return d;
}
__device__ __forceinline__ uint64_t pack2(float x, float y) {
    uint64_t d;
    asm("mov.b64 %0, {%1, %2};" : "=l"(d) : "f"(x), "f"(y));
    return d;
}
__device__ __forceinline__ void unpack2(uint64_t v, float& lo, float& hi) {
    asm("mov.b64 {%0, %1}, %2;" : "=f"(lo), "=f"(hi) : "l"(v));
}
__device__ __forceinline__ void lds_v2u64(uint64_t& a, uint64_t& b, uint32_t addr) {
    asm volatile("ld.shared.v2.u64 {%0, %1}, [%2];" : "=l"(a), "=l"(b) : "r"(addr));
}

#define MBARRIER_INIT(addr, count) \
    asm volatile("mbarrier.init.shared.b64 [%0], %1;" \
                 :: "r"((uint32_t)(addr)), "r"((uint32_t)(count)) : "memory")

#define MBARRIER_WAIT_PARITY(mbar_smem_addr, phase_parity) do { \
    uint32_t _mbar = (uint32_t)(mbar_smem_addr); \
    uint32_t _parity = (uint32_t)(phase_parity); \
    uint32_t _done; \
    asm volatile( \
        "{\n\t" \
        ".reg .pred p;\n\t" \
        "mbarrier.try_wait.parity.acquire.cta.shared::cta.b64 p, [%1], %2;\n\t" \
        "selp.b32 %0, 1, 0, p;\n\t" \
        "}" \
        : "=r"(_done) : "r"(_mbar), "r"(_parity) : "memory"); \
    if (!_done) { \
        asm volatile( \
            "{\n\t" \
            ".reg .pred P1;\n\t" \
            "WAIT_LOOP_%=:\n\t" \
            "mbarrier.try_wait.parity.acquire.cta.shared::cta.b64 P1, [%0], %1, 0x989680;\n\t" \
            "@P1 bra.uni WAIT_DONE_%=;\n\t" \
            "bra.uni WAIT_LOOP_%=;\n\t" \
            "WAIT_DONE_%=:\n\t" \
            "}" \
            :: "r"(_mbar), "r"(_parity) : "memory"); \
    } \
} while(0)

#define CLUSTER_SYNC() do { \
    asm volatile("barrier.cluster.arrive.aligned;" ::: "memory"); \
    asm volatile("barrier.cluster.wait.aligned;"   ::: "memory"); \
} while (0)

// ---------------------------------------------------------------------------
// GEMM: out[M x 1024] = A[M x K] @ W[K x 1024] + bias   (M = 65536)
// (R10/R12-proven version: 64x64 tile, K chunked by 128, 66 KB smem,
//  pack2 splats in the inner loop. The R13 pre-splatted-A variant raced.)
// ---------------------------------------------------------------------------
template <int K>
__global__ __launch_bounds__(256)
void gemm_xw(const float* __restrict__ A, const float* __restrict__ W,
             const float* __restrict__ bias, float* __restrict__ out) {
    extern __shared__ float sm[];
    float* a_s = sm;               // [128][65] transposed A tile
    float* w_s = sm + 128 * 65;    // [128][64]

    const int tid = threadIdx.x;
    const long m0 = (long)blockIdx.x * 64;
    const int  n0 = blockIdx.y * 64;

    const int tn = (tid & 15) << 2;
    const int tm = (tid >> 4) << 2;

    const uint32_t ws_b = (uint32_t)__cvta_generic_to_shared(w_s);

    uint64_t acc01[4], acc23[4];
#pragma unroll
    for (int i = 0; i < 4; i++) { acc01[i] = 0ull; acc23[i] = 0ull; }

    for (int k0 = 0; k0 < K; k0 += 128) {
        for (int idx = tid; idx < 64 * 128; idx += 256) {
            int r = idx >> 7;
            int k = idx & 127;
            a_s[k * 65 + r] = A[(m0 + r) * K + k0 + k];
        }
        for (int idx = tid; idx < 128 * 16; idx += 256) {
            int k = idx >> 4, c4 = idx & 15;
            *reinterpret_cast<float4*>(w_s + k * 64 + c4 * 4) =
                *reinterpret_cast<const float4*>(W + (size_t)(k0 + k) * G4H + n0 + c4 * 4);
        }
        __syncthreads();

#pragma unroll 8
        for (int k = 0; k < 128; k++) {
            const float* ap = a_s + k * 65 + tm;
            float a0 = ap[0], a1 = ap[1], a2 = ap[2], a3 = ap[3];
            uint64_t b01, b23;
            lds_v2u64(b01, b23, ws_b + (uint32_t)(k * 64 + tn) * 4u);
            uint64_t aa;
            aa = pack2(a0, a0);
            acc01[0] = fma_x2(aa, b01, acc01[0]); acc23[0] = fma_x2(aa, b23, acc23[0]);
            aa = pack2(a1, a1);
            acc01[1] = fma_x2(aa, b01, acc01[1]); acc23[1] = fma_x2(aa, b23, acc23[1]);
            aa = pack2(a2, a2);
            acc01[2] = fma_x2(aa, b01, acc01[2]); acc23[2] = fma_x2(aa, b23, acc23[2]);
            aa = pack2(a3, a3);
            acc01[3] = fma_x2(aa, b01, acc01[3]); acc23[3] = fma_x2(aa, b23, acc23[3]);
        }
        __syncthreads();
    }

    float4 bv = *reinterpret_cast<const float4*>(bias + n0 + tn);
#pragma unroll
    for (int i = 0; i < 4; i++) {
        float4 o;
        unpack2(acc01[i], o.x, o.y);
        unpack2(acc23[i], o.z, o.w);
        o.x += bv.x; o.y += bv.y; o.z += bv.z; o.w += bv.w;
        *reinterpret_cast<float4*>(out + (m0 + tm + i) * G4H + n0 + tn) = o;
    }
}

// ---------------------------------------------------------------------------
// LSTM recurrence — R10 VERBATIM (best measured: 8875us). 4-way k-split,
// register-resident U, per-thread push store + plain arrive, acquire.cta
// waits. This round re-validates its stability (rel_err watch: ~1.3e-4
// expected; material drift would confirm a store/arrive ordering race).
// ---------------------------------------------------------------------------
__device__ __forceinline__ float sigmoidf_(float x) {
    return __fdividef(1.f, 1.f + __expf(-x));
}

#define HBUF_OFF    0                             // [2 parity][2 batch][256]
#define PART_OFF    (2 * 2 * HDIM)                // [4 kq][4 gate][2 b][32]
#define MBAR_OFF    (PART_OFF + 1024)             // 2 x u64 (8B aligned)
#define REC_FLOATS  (MBAR_OFF + 8)
#define REC_THREADS 512

template <bool STORE_SEQ>
__global__ __launch_bounds__(REC_THREADS, 1) __cluster_dims__(CLUSTER_SZ, 1, 1)
void lstm_rec(const float* __restrict__ xw, const float* __restrict__ U,
              float* __restrict__ out_seq, float* __restrict__ out_last) {
    extern __shared__ float sm[];
    float* hbuf = sm + HBUF_OFF;
    float* part = sm + PART_OFF;

    const int tid = threadIdx.x;        // 512
    const int kq  = tid >> 7;           // k-quarter 0..3
    const int g   = (tid >> 5) & 3;     // gate 0..3 (i,f,g,o)
    const int u   = tid & 31;           // unit within CTA slice

    uint32_t rank;
    asm("mov.u32 %0, %%cluster_ctarank;" : "=r"(rank));
    const int cid = blockIdx.x >> 3;
    const int u0  = (int)rank * 32;
    const int b0  = cid * 2;

    const uint32_t smem_b = (uint32_t)__cvta_generic_to_shared(sm);
    const uint32_t mbar_b = smem_b + MBAR_OFF * 4u;
    const uint32_t hbuf_b = smem_b + HBUF_OFF * 4u;

    if (tid == 0) {
        MBARRIER_INIT(mbar_b,      512);   // parity buffer 0
        MBARRIER_INIT(mbar_b + 8,  512);   // parity buffer 1
    }

    // ---- This thread's 64 U weights -> 32 packed f32x2 registers.
    const int gcol = g * HDIM + u0 + u;
    uint64_t wreg[32];
    {
        const float* Up = U + (size_t)(kq * 64) * G4H + gcol;
#pragma unroll
        for (int k4 = 0; k4 < 16; k4++) {
            float w0 = Up[(k4 * 4 + 0) * G4H];
            float w1 = Up[(k4 * 4 + 1) * G4H];
            float w2 = Up[(k4 * 4 + 2) * G4H];
            float w3 = Up[(k4 * 4 + 3) * G4H];
            wreg[k4 * 2 + 0] = pack2(w0, w1);
            wreg[k4 * 2 + 1] = pack2(w2, w3);
        }
    }

    // Zero h double-buffer + partials
    for (int idx = tid; idx < 2 * 2 * HDIM + 1024; idx += REC_THREADS)
        hbuf[idx] = 0.f;
    __syncthreads();

    // Combine-thread state (warps 0/1)
    const bool is_comb = (tid < 64);
    const int  cb  = tid >> 5;          // batch within pair
    const int  cu  = tid & 31;          // unit
    float cst = 0.f;
    float xwr0 = 0.f, xwr1 = 0.f, xwr2 = 0.f, xwr3 = 0.f;
    const size_t xbase = (size_t)(b0 + cb) * T_STEPS * G4H + u0 + cu;
    uint32_t ra_base[CLUSTER_SZ];       // mapa'd peer SMEM bases (combine only)
    if (is_comb) {
        xwr0 = xw[xbase + 0 * HDIM];
        xwr1 = xw[xbase + 1 * HDIM];
        xwr2 = xw[xbase + 2 * HDIM];
        xwr3 = xw[xbase + 3 * HDIM];
#pragma unroll
        for (int r = 0; r < CLUSTER_SZ; r++) {
            asm volatile("mapa.shared::cluster.u32 %0, %1, %2;"
                         : "=r"(ra_base[r]) : "r"(smem_b), "r"(r));
        }
    }

    // mbarriers + zeroed hbuf must be cluster-visible before any peer store.
    CLUSTER_SYNC();

    int ph0 = 0, ph1 = 0;

    for (int t = 0; t < T_STEPS; t++) {
        // Wait for h(t-1): lives in buf[(t+1)&1], signaled on mbar[(t+1)&1]
        if (t > 0) {
            if (t & 1) { MBARRIER_WAIT_PARITY(mbar_b,     ph0); ph0 ^= 1; }
            else       { MBARRIER_WAIT_PARITY(mbar_b + 8, ph1); ph1 ^= 1; }
        }

        const int rd = (t + 1) & 1;
        const uint32_t h0_b = hbuf_b + (uint32_t)(rd * 2 * HDIM + kq * 64) * 4u;
        const uint32_t h1_b = h0_b + HDIM * 4u;

        uint64_t a01 = 0ull, a23 = 0ull, c01 = 0ull, c23 = 0ull;
#pragma unroll
        for (int k4 = 0; k4 < 16; k4++) {
            uint64_t p01, p23, q01, q23;
            lds_v2u64(p01, p23, h0_b + (uint32_t)k4 * 16u);  // broadcast
            lds_v2u64(q01, q23, h1_b + (uint32_t)k4 * 16u);  // broadcast
            a01 = fma_x2(wreg[k4 * 2 + 0], p01, a01);
            a23 = fma_x2(wreg[k4 * 2 + 1], p23, a23);
            c01 = fma_x2(wreg[k4 * 2 + 0], q01, c01);
            c23 = fma_x2(wreg[k4 * 2 + 1], q23, c23);
        }
        float s0, s1, s2, s3, r0, r1, r2, r3;
        unpack2(a01, s0, s1); unpack2(a23, s2, s3);
        unpack2(c01, r0, r1); unpack2(c23, r2, r3);
        float pa = (s0 + s1) + (s2 + s3);
        float pb = (r0 + r1) + (r2 + r3);

        // part[kq][gate][batch][unit] — u consecutive per warp: conflict-free
        part[((kq * 4 + g) * 2 + 0) * 32 + u] = pa;
        part[((kq * 4 + g) * 2 + 1) * 32 + u] = pb;
        __syncthreads();

        if (is_comb) {
            float zi = xwr0, zf = xwr1, zg = xwr2, zo = xwr3;
#pragma unroll
            for (int q = 0; q < 4; q++) {
                zi += part[((q * 4 + 0) * 2 + cb) * 32 + cu];
                zf += part[((q * 4 + 1) * 2 + cb) * 32 + cu];
                zg += part[((q * 4 + 2) * 2 + cb) * 32 + cu];
                zo += part[((q * 4 + 3) * 2 + cb) * 32 + cu];
            }

            float iv = sigmoidf_(zi);
            float fv = sigmoidf_(zf);
            float ov = sigmoidf_(zo);
            cst = fmaf(fv, cst, iv * zg);  // linear candidate activation
            float h = ov * cst;            // linear output activation

            if (STORE_SEQ) {
                out_seq[((size_t)(b0 + cb) * T_STEPS + t) * HDIM + u0 + cu] = h;
            } else if (t == T_STEPS - 1) {
                out_last[(b0 + cb) * HDIM + u0 + cu] = h;
            }

            if (t + 1 < T_STEPS) {
                // R4 signaling: push h(t) slice to all 8 peers' buf[t&1],
                // then arrive on each peer's mbar[t&1] (fire-and-forget).
                const uint32_t hoff = HBUF_OFF * 4u +
                    ((uint32_t)((t & 1) * 2 * HDIM + cb * HDIM + u0 + cu) << 2);
#pragma unroll
                for (int r = 0; r < CLUSTER_SZ; r++) {
                    asm volatile("st.shared::cluster.f32 [%0], %1;"
                                 :: "r"(ra_base[r] + hoff), "f"(h) : "memory");
                }
                const uint32_t moff = MBAR_OFF * 4u + ((uint32_t)(t & 1) << 3);
#pragma unroll
                for (int r = 0; r < CLUSTER_SZ; r++) {
                    asm volatile("mbarrier.arrive.shared::cluster.b64 _, [%0];"
                                 :: "r"(ra_base[r] + moff) : "memory");
                }
            }

            // prefetch next step's xw (after the signal is on the wire)
            if (t + 1 < T_STEPS) {
                const size_t xb = xbase + (size_t)(t + 1) * G4H;
                xwr0 = xw[xb + 0 * HDIM];
                xwr1 = xw[xb + 1 * HDIM];
                xwr2 = xw[xb + 2 * HDIM];
                xwr3 = xw[xb + 3 * HDIM];
            }
        }
        // No end-of-step barrier: next-step part/hbuf writes are ordered
        // behind the mbar wait (which requires this CTA's own arrives).
    }
}

// ---------------------------------------------------------------------------
// Final FC: out[32,1,128] = h1T[32,256] @ Wfc[256,128] + bfc
// ---------------------------------------------------------------------------
__global__ __launch_bounds__(128)
void fc_kernel(const float* __restrict__ h, const float* __restrict__ Wfc,
               const float* __restrict__ bfc, float* __restrict__ out) {
    const int b = blockIdx.x;
    const int j = threadIdx.x;
    const float* hb = h + b * HDIM;
    float acc = bfc[j];
#pragma unroll 16
    for (int k = 0; k < HDIM; k++)
        acc = fmaf(hb[k], Wfc[k * 128 + j], acc);
    out[b * 128 + j] = acc;
}

// ---------------------------------------------------------------------------
// Launch
// ---------------------------------------------------------------------------
#define GEMM_SMEM ((128 * 65 + 128 * 64) * 4)   // 66048
#define REC_SMEM  (REC_FLOATS * 4)              // ~8 KB

extern "C" void kernel_launch(void* const* d_in, const int* in_sizes, int n_in,
                              void* d_out, int out_size) {
    const float* x   = (const float*)d_in[0];
    const float* W0  = (const float*)d_in[1];
    const float* U0  = (const float*)d_in[2];
    const float* b0v = (const float*)d_in[3];
    const float* W1  = (const float*)d_in[4];
    const float* U1  = (const float*)d_in[5];
    const float* b1v = (const float*)d_in[6];
    const float* Wfc = (const float*)d_in[7];
    const float* bfc = (const float*)d_in[8];
    float* out = (float*)d_out;

    float *xw0, *h0seq, *xw1, *h1T;
    cudaGetSymbolAddress((void**)&xw0,   g_xw0);
    cudaGetSymbolAddress((void**)&h0seq, g_h0seq);
    cudaGetSymbolAddress((void**)&xw1,   g_xw1);
    cudaGetSymbolAddress((void**)&h1T,   g_h1T);

    cudaFuncSetAttribute(gemm_xw<128>, cudaFuncAttributeMaxDynamicSharedMemorySize, GEMM_SMEM);
    cudaFuncSetAttribute(gemm_xw<256>, cudaFuncAttributeMaxDynamicSharedMemorySize, GEMM_SMEM);
    cudaFuncSetAttribute(lstm_rec<true>,  cudaFuncAttributeMaxDynamicSharedMemorySize, REC_SMEM);
    cudaFuncSetAttribute(lstm_rec<false>, cudaFuncAttributeMaxDynamicSharedMemorySize, REC_SMEM);

    const long M = (long)NB * T_STEPS;  // 65536 rows

    gemm_xw<128><<<dim3((unsigned)(M / 64), G4H / 64), 256, GEMM_SMEM>>>(x, W0, b0v, xw0);
    lstm_rec<true><<<NB / 2 * CLUSTER_SZ, REC_THREADS, REC_SMEM>>>(xw0, U0, h0seq, nullptr);
    gemm_xw<256><<<dim3((unsigned)(M / 64), G4H / 64), 256, GEMM_SMEM>>>(h0seq, W1, b1v, xw1);
    lstm_rec<false><<<NB / 2 * CLUSTER_SZ, REC_THREADS, REC_SMEM>>>(xw1, U1, nullptr, h1T);
    fc_kernel<<<NB, 128>>>(h1T, Wfc, bfc, out);
}